// round 1
// baseline (speedup 1.0000x reference)
#include <cuda_runtime.h>

// Problem constants
#define NB    8
#define NTOK  16384
#define NC    256
#define NG    256     // windows per batch (16x16)
#define NS    64      // tokens per window (8x8)
#define NWIN  (NB*NG) // 2048
#define QKVW  768     // q(256) | k(256) | v(256)

// Scratch: windowed Q|K|V rows. Attention output overwrites the Q columns.
// 2048 windows * 64 rows * 768 floats = 100,663,296 floats (384 MB)
__device__ float g_qkv[(size_t)NWIN * NS * QKVW];

// ---------------------------------------------------------------------------
// Kernel A: g_qkv[win][s][cb*64 .. cb*64+63] = in_window @ W^T  (tiled GEMM)
//   cb 0..7  -> input=query, W = W_qk rows [cb*64, cb*64+64)
//   cb 8..11 -> input=x,     W = W_v  rows [(cb-8)*64, ...)
// ---------------------------------------------------------------------------
__global__ __launch_bounds__(256) void qkv_kernel(
    const float* __restrict__ x, const float* __restrict__ query,
    const float* __restrict__ W_qk, const float* __restrict__ W_v)
{
    extern __shared__ float4 sm4[];
    float4* s_a = sm4;            // 64 rows x 65 float4 (padded)
    float4* s_w = sm4 + 64 * 65;  // 64 rows x 65 float4

    const int win = blockIdx.x;   // 0..2047
    const int cb  = blockIdx.y;   // 0..11
    const int b  = win >> 8;
    const int g  = win & 255;
    const int ga = g >> 4, gw = g & 15;

    const float4* in4 = (const float4*)((cb < 8) ? query : x);
    const float4* w4  = (cb < 8) ? ((const float4*)W_qk + cb * 64 * 64)
                                 : ((const float4*)W_v  + (cb - 8) * 64 * 64);

    const int tid = threadIdx.x;
    const long tokbase = (long)b * NTOK;

    // Gather the 64 window-token rows (256 floats each) of the input
    for (int idx = tid; idx < 64 * 64; idx += 256) {
        int s = idx >> 6, c4 = idx & 63;
        int n = ((ga * 8 + (s >> 3)) << 7) + gw * 8 + (s & 7);
        s_a[s * 65 + c4] = in4[(tokbase + n) * 64 + c4];
    }
    // 64 weight rows
    for (int idx = tid; idx < 64 * 64; idx += 256) {
        int r = idx >> 6, c4 = idx & 63;
        s_w[r * 65 + c4] = w4[r * 64 + c4];
    }
    __syncthreads();

    const int ty = tid >> 4, tx = tid & 15;
    float acc[4][4];
    #pragma unroll
    for (int i = 0; i < 4; i++)
        #pragma unroll
        for (int j = 0; j < 4; j++) acc[i][j] = 0.f;

    #pragma unroll 4
    for (int c4 = 0; c4 < 64; ++c4) {
        float4 av[4], wv[4];
        #pragma unroll
        for (int i = 0; i < 4; i++) av[i] = s_a[(ty * 4 + i) * 65 + c4];
        #pragma unroll
        for (int j = 0; j < 4; j++) wv[j] = s_w[(tx * 4 + j) * 65 + c4];
        #pragma unroll
        for (int i = 0; i < 4; i++)
            #pragma unroll
            for (int j = 0; j < 4; j++)
                acc[i][j] += av[i].x * wv[j].x + av[i].y * wv[j].y +
                             av[i].z * wv[j].z + av[i].w * wv[j].w;
    }

    float* outp = g_qkv + (long)win * 64 * QKVW + cb * 64;
    #pragma unroll
    for (int i = 0; i < 4; i++) {
        int r = ty * 4 + i;
        float4 v = make_float4(acc[i][0], acc[i][1], acc[i][2], acc[i][3]);
        *((float4*)(outp + (long)r * QKVW) + tx) = v;
    }
}

// ---------------------------------------------------------------------------
// Kernel B: per-window attention with talking heads.
//   scores -> @W_pre^T -> exp -> /sum_k -> @W_post^T -> @V
// Output overwrites g_qkv Q columns (0..255) for this window's rows.
// ---------------------------------------------------------------------------
#define AP 4168   // attn plane stride (floats): 64*65 + 8  (2-way worst conflicts)
#define AR 65     // attn row stride (floats): conflict-free for lane-varying q

__global__ __launch_bounds__(256) void attn_kernel(
    const float* __restrict__ W_pre, const float* __restrict__ W_post)
{
    extern __shared__ float sm[];
    float4* s_kv4  = (float4*)sm;        // 64 x 65 float4 (K, later V)
    float*  s_attn = sm + 16640;         // 8 planes x AP
    float*  s_wpre  = sm + 16640 + 8 * AP;        // 64
    float*  s_wpost = sm + 16640 + 8 * AP + 64;   // 64
    float*  s_rsum  = sm + 16640 + 8 * AP + 128;  // 512

    const int win = blockIdx.x;
    const int tid = threadIdx.x;
    const int qrow = tid & 63;
    const int hp   = tid >> 6;          // head pair 0..3
    const long rowbase = (long)win * 64;
    const float4* qkv4 = (const float4*)g_qkv;   // row stride 192 float4

    // Stage K (cols 256..511)
    for (int idx = tid; idx < 64 * 64; idx += 256) {
        int s = idx >> 6, c4 = idx & 63;
        s_kv4[s * 65 + c4] = qkv4[(rowbase + s) * 192 + 64 + c4];
    }
    if (tid < 64) { s_wpre[tid] = W_pre[tid]; s_wpost[tid] = W_post[tid]; }

    // Q row for this thread (heads 2*hp, 2*hp+1) into registers
    float4 qr[16];
    #pragma unroll
    for (int j4 = 0; j4 < 16; j4++)
        qr[j4] = qkv4[(rowbase + qrow) * 192 + hp * 16 + j4];
    __syncthreads();

    // ---- scores: s_attn[h][qrow][k] = scale * q.k ----
    const float scale = 0.17677669529663687f;   // 32^-0.5
    for (int k = 0; k < 64; k++) {
        #pragma unroll
        for (int h2 = 0; h2 < 2; h2++) {
            int h = hp * 2 + h2;
            float acc = 0.f;
            #pragma unroll
            for (int d4 = 0; d4 < 8; ++d4) {
                float4 kv = s_kv4[k * 65 + h * 8 + d4];  // broadcast across lanes
                float4 qv = qr[h2 * 8 + d4];
                acc += qv.x * kv.x + qv.y * kv.y + qv.z * kv.z + qv.w * kv.w;
            }
            s_attn[h * AP + qrow * AR + k] = acc * scale;
        }
    }
    __syncthreads();

    // ---- pre-mix (attn @ W_pre^T over heads) + exp ----
    #pragma unroll 1
    for (int i = 0; i < 16; i++) {
        int p = tid + (i << 8);          // (q,k) pair, lanes vary k
        int q = p >> 6, k = p & 63;
        float av[8], m[8];
        #pragma unroll
        for (int h = 0; h < 8; h++) av[h] = s_attn[h * AP + q * AR + k];
        #pragma unroll
        for (int h = 0; h < 8; h++) {
            float s = 0.f;
            #pragma unroll
            for (int h2 = 0; h2 < 8; h2++) s += av[h2] * s_wpre[h * 8 + h2];
            m[h] = __expf(s);
        }
        #pragma unroll
        for (int h = 0; h < 8; h++) s_attn[h * AP + q * AR + k] = m[h];
    }
    __syncthreads();

    // ---- softmax denominator over k per (q,h) ----
    #pragma unroll
    for (int i = 0; i < 2; i++) {
        int task = tid + (i << 8);
        int q = task >> 3, h = task & 7;
        float s = 0.f;
        #pragma unroll 8
        for (int k = 0; k < 64; k++) s += s_attn[h * AP + q * AR + k];
        s_rsum[task] = 1.0f / s;
    }
    __syncthreads();

    // ---- normalize + post-mix (attn @ W_post^T) ----
    #pragma unroll 1
    for (int i = 0; i < 16; i++) {
        int p = tid + (i << 8);
        int q = p >> 6, k = p & 63;
        float av[8], m[8];
        #pragma unroll
        for (int h = 0; h < 8; h++)
            av[h] = s_attn[h * AP + q * AR + k] * s_rsum[q * 8 + h];
        #pragma unroll
        for (int h = 0; h < 8; h++) {
            float s = 0.f;
            #pragma unroll
            for (int h2 = 0; h2 < 8; h2++) s += av[h2] * s_wpost[h * 8 + h2];
            m[h] = s;
        }
        #pragma unroll
        for (int h = 0; h < 8; h++) s_attn[h * AP + q * AR + k] = m[h];
    }
    __syncthreads();

    // Stage V (cols 512..767) over the K buffer
    for (int idx = tid; idx < 64 * 64; idx += 256) {
        int s = idx >> 6, c4 = idx & 63;
        s_kv4[s * 65 + c4] = qkv4[(rowbase + s) * 192 + 128 + c4];
    }
    __syncthreads();

    // ---- out[qrow, h, d] = sum_k attn[h][qrow][k] * v[k, h, d] ----
    float4 o[16];
    #pragma unroll
    for (int j = 0; j < 16; j++) o[j] = make_float4(0.f, 0.f, 0.f, 0.f);
    const int h0 = hp * 2, h1 = hp * 2 + 1;
    for (int k = 0; k < 64; k++) {
        float a0 = s_attn[h0 * AP + qrow * AR + k];
        float a1 = s_attn[h1 * AP + qrow * AR + k];
        #pragma unroll
        for (int d4 = 0; d4 < 8; ++d4) {
            float4 v = s_kv4[k * 65 + h0 * 8 + d4];
            o[d4].x += a0 * v.x; o[d4].y += a0 * v.y;
            o[d4].z += a0 * v.z; o[d4].w += a0 * v.w;
        }
        #pragma unroll
        for (int d4 = 0; d4 < 8; ++d4) {
            float4 v = s_kv4[k * 65 + h1 * 8 + d4];
            o[8 + d4].x += a1 * v.x; o[8 + d4].y += a1 * v.y;
            o[8 + d4].z += a1 * v.z; o[8 + d4].w += a1 * v.w;
        }
    }
    // write over Q columns of this window's rows (Q is dead)
    float4* qkvw = (float4*)g_qkv;
    #pragma unroll
    for (int j4 = 0; j4 < 16; j4++)
        qkvw[(rowbase + qrow) * 192 + hp * 16 + j4] = o[j4];
}

// ---------------------------------------------------------------------------
// Kernel C: out = unwindow(attn_out) @ W_proj^T + b_proj  (row-gather GEMM)
// ---------------------------------------------------------------------------
__global__ __launch_bounds__(256) void proj_kernel(
    const float* __restrict__ W_proj, const float* __restrict__ b_proj,
    float* __restrict__ out)
{
    extern __shared__ float4 sm4[];
    float4* s_a = sm4;
    float4* s_w = sm4 + 64 * 65;

    const int tile = blockIdx.x;   // 0..2047 over 131072 output rows
    const int cb   = blockIdx.y;   // 0..3
    const int tid  = threadIdx.x;
    const long row0 = (long)tile * 64;
    const float4* qkv4 = (const float4*)g_qkv;

    // gather 64 token rows from windowed layout (attn output in cols 0..255)
    for (int idx = tid; idx < 64 * 64; idx += 256) {
        int s = idx >> 6, c4 = idx & 63;
        long row = row0 + s;
        int b = (int)(row >> 14);
        int n = (int)(row & 16383);
        int i = n >> 7, j = n & 127;
        int srcrow = ((b << 8) + (i >> 3) * 16 + (j >> 3)) * 64 + (i & 7) * 8 + (j & 7);
        s_a[s * 65 + c4] = qkv4[(long)srcrow * 192 + c4];
    }
    const float4* w4 = (const float4*)W_proj + cb * 64 * 64;
    for (int idx = tid; idx < 64 * 64; idx += 256) {
        int r = idx >> 6, c4 = idx & 63;
        s_w[r * 65 + c4] = w4[r * 64 + c4];
    }
    __syncthreads();

    const int ty = tid >> 4, tx = tid & 15;
    float acc[4][4];
    #pragma unroll
    for (int i = 0; i < 4; i++)
        #pragma unroll
        for (int j = 0; j < 4; j++) acc[i][j] = 0.f;

    #pragma unroll 4
    for (int c4 = 0; c4 < 64; ++c4) {
        float4 av[4], wv[4];
        #pragma unroll
        for (int i = 0; i < 4; i++) av[i] = s_a[(ty * 4 + i) * 65 + c4];
        #pragma unroll
        for (int j = 0; j < 4; j++) wv[j] = s_w[(tx * 4 + j) * 65 + c4];
        #pragma unroll
        for (int i = 0; i < 4; i++)
            #pragma unroll
            for (int j = 0; j < 4; j++)
                acc[i][j] += av[i].x * wv[j].x + av[i].y * wv[j].y +
                             av[i].z * wv[j].z + av[i].w * wv[j].w;
    }

    const int col0 = cb * 64 + tx * 4;
    float4 bias = *(const float4*)(b_proj + col0);
    #pragma unroll
    for (int i = 0; i < 4; i++) {
        float4 v = make_float4(acc[i][0] + bias.x, acc[i][1] + bias.y,
                               acc[i][2] + bias.z, acc[i][3] + bias.w);
        *(float4*)(out + (row0 + ty * 4 + i) * NC + col0) = v;
    }
}

// ---------------------------------------------------------------------------
extern "C" void kernel_launch(void* const* d_in, const int* in_sizes, int n_in,
                              void* d_out, int out_size)
{
    const float* x      = (const float*)d_in[0];
    const float* query  = (const float*)d_in[1];
    const float* W_qk   = (const float*)d_in[2];
    const float* W_v    = (const float*)d_in[3];
    const float* W_proj = (const float*)d_in[4];
    const float* b_proj = (const float*)d_in[5];
    const float* W_pre  = (const float*)d_in[6];
    const float* W_post = (const float*)d_in[7];
    float* out = (float*)d_out;

    const int SMEM_GEMM = 2 * 64 * 65 * 16;                         // 133,120 B
    const int SMEM_ATTN = (16640 + 8 * AP + 128 + 512) * 4;         // 202,496 B

    cudaFuncSetAttribute(qkv_kernel,  cudaFuncAttributeMaxDynamicSharedMemorySize, SMEM_GEMM);
    cudaFuncSetAttribute(attn_kernel, cudaFuncAttributeMaxDynamicSharedMemorySize, SMEM_ATTN);
    cudaFuncSetAttribute(proj_kernel, cudaFuncAttributeMaxDynamicSharedMemorySize, SMEM_GEMM);

    qkv_kernel<<<dim3(NWIN, 12), 256, SMEM_GEMM>>>(x, query, W_qk, W_v);
    attn_kernel<<<NWIN, 256, SMEM_ATTN>>>(W_pre, W_post);
    proj_kernel<<<dim3(NWIN, 4), 256, SMEM_GEMM>>>(W_proj, b_proj, out);
}

// round 2
// speedup vs baseline: 4.6857x; 4.6857x over previous
#include <cuda_runtime.h>
#include <cstdint>

// Problem constants
#define NB    8
#define NTOK  16384
#define NC    256
#define NWIN  2048    // B * (16x16 windows)
#define QKVW  768     // q(256) | k(256) | v(256)

// Scratch: windowed Q|K|V rows. Attention output overwrites the Q columns.
__device__ float g_qkv[(size_t)NWIN * 64 * QKVW];

// ---------------------------------------------------------------------------
// tf32 mma helpers
// ---------------------------------------------------------------------------
__device__ __forceinline__ uint32_t f2tf(float f) {
    uint32_t u;
    asm("cvt.rna.tf32.f32 %0, %1;" : "=r"(u) : "f"(f));
    return u;
}
__device__ __forceinline__ void mma_tf32(float c[4],
    uint32_t a0, uint32_t a1, uint32_t a2, uint32_t a3,
    uint32_t b0, uint32_t b1)
{
    asm volatile(
        "mma.sync.aligned.m16n8k8.row.col.f32.tf32.tf32.f32 "
        "{%0,%1,%2,%3},{%4,%5,%6,%7},{%8,%9},{%0,%1,%2,%3};"
        : "+f"(c[0]), "+f"(c[1]), "+f"(c[2]), "+f"(c[3])
        : "r"(a0), "r"(a1), "r"(a2), "r"(a3), "r"(b0), "r"(b1));
}
#define CPA16(dst, src) \
    asm volatile("cp.async.cg.shared.global [%0],[%1],16;" :: "r"(dst), "l"(src))
#define CP_COMMIT() asm volatile("cp.async.commit_group;")
#define CP_WAIT0()  asm volatile("cp.async.wait_group 0;" ::: "memory")

// Shared tile geometry: A/B tiles 128 rows x 32 k, stored with 36-float stride
// (bank = (4*row + k) mod 32 -> conflict-free mma fragment LDS).
#define TSTRIDE 36
#define TILE_F  (128 * TSTRIDE)          // floats per tile (4608)
#define BUF_F   (2 * TILE_F)             // A + B per buffer (9216)
#define SMEM_MMA_BYTES (2 * BUF_F * 4)   // double buffered (73728 B)

// ---------------------------------------------------------------------------
// Kernel A (tf32 mma): windowed-gather GEMM producing Q|K|V.
//   blockIdx.x = window pair (rows 128), blockIdx.y = 128-col block (0..5):
//   cb 0..3 -> input=query, W=W_qk rows [cb*128), dest col cb*128  (Q|K)
//   cb 4..5 -> input=x,     W=W_v rows [(cb-4)*128), dest col 512+(cb-4)*128 (V)
// ---------------------------------------------------------------------------
__global__ __launch_bounds__(256) void qkv_mma(
    const float* __restrict__ x, const float* __restrict__ query,
    const float* __restrict__ W_qk, const float* __restrict__ W_v)
{
    extern __shared__ float sm[];
    const int tid = threadIdx.x;
    const int p   = blockIdx.x;
    const int cb  = blockIdx.y;

    const float* in = (cb < 4) ? query : x;
    const float* Wt = (cb < 4) ? (W_qk + (long)cb * 128 * 256)
                               : (W_v  + (long)(cb - 4) * 128 * 256);
    const int dstcol = (cb < 4) ? cb * 128 : 512 + (cb - 4) * 128;

    // --- per-thread gmem->smem assignment: row = tid/2, 16-float half = tid%2
    const int ldr = tid >> 1;
    const int ldc = (tid & 1) << 4;
    {
        // nothing
    }
    int win = p * 2 + (ldr >> 6);
    int s   = ldr & 63;
    int b   = win >> 8, g = win & 255;
    int n   = ((g >> 4) * 8 + (s >> 3)) * 128 + (g & 15) * 8 + (s & 7);
    const float* a_src0 = in + ((long)b * NTOK + n) * 256 + ldc;
    const float* b_src0 = Wt + (long)ldr * 256 + ldc;

    uint32_t smem_base = (uint32_t)__cvta_generic_to_shared(sm);
    uint32_t a_dst0 = smem_base + (uint32_t)(ldr * TSTRIDE + ldc) * 4;
    uint32_t b_dst0 = a_dst0 + TILE_F * 4;

    const int lane = tid & 31, w = tid >> 5;
    const int wm = (w >> 1) * 32;      // warp row base in tile
    const int wn = (w & 1) * 64;       // warp col base in tile
    const int gq = lane >> 2, tg = lane & 3;

    float acc[2][8][4];
    #pragma unroll
    for (int mt = 0; mt < 2; mt++)
        #pragma unroll
        for (int nt = 0; nt < 8; nt++)
            #pragma unroll
            for (int q = 0; q < 4; q++) acc[mt][nt][q] = 0.f;

    // prologue: k-block 0 into buffer 0
    {
        const float* as = a_src0;
        const float* bs = b_src0;
        #pragma unroll
        for (int i = 0; i < 4; i++) CPA16(a_dst0 + i * 16, as + i * 4);
        #pragma unroll
        for (int i = 0; i < 4; i++) CPA16(b_dst0 + i * 16, bs + i * 4);
        CP_COMMIT();
    }

    for (int kb = 0; kb < 8; ++kb) {
        CP_WAIT0();
        __syncthreads();
        if (kb < 7) {
            uint32_t off = (uint32_t)(((kb + 1) & 1) * BUF_F * 4);
            const float* as = a_src0 + (kb + 1) * 32;
            const float* bs = b_src0 + (kb + 1) * 32;
            #pragma unroll
            for (int i = 0; i < 4; i++) CPA16(a_dst0 + off + i * 16, as + i * 4);
            #pragma unroll
            for (int i = 0; i < 4; i++) CPA16(b_dst0 + off + i * 16, bs + i * 4);
            CP_COMMIT();
        }
        const float* sA = sm + (kb & 1) * BUF_F;
        const float* sB = sA + TILE_F;

        #pragma unroll
        for (int ks = 0; ks < 4; ++ks) {
            const int k0 = ks * 8;
            uint32_t af[2][4];
            #pragma unroll
            for (int mt = 0; mt < 2; mt++) {
                const int r0 = wm + mt * 16;
                af[mt][0] = f2tf(sA[(r0 + gq)     * TSTRIDE + k0 + tg]);
                af[mt][1] = f2tf(sA[(r0 + gq + 8) * TSTRIDE + k0 + tg]);
                af[mt][2] = f2tf(sA[(r0 + gq)     * TSTRIDE + k0 + tg + 4]);
                af[mt][3] = f2tf(sA[(r0 + gq + 8) * TSTRIDE + k0 + tg + 4]);
            }
            #pragma unroll
            for (int nt = 0; nt < 8; nt++) {
                const int nb = wn + nt * 8;
                uint32_t b0 = f2tf(sB[(nb + gq) * TSTRIDE + k0 + tg]);
                uint32_t b1 = f2tf(sB[(nb + gq) * TSTRIDE + k0 + tg + 4]);
                mma_tf32(acc[0][nt], af[0][0], af[0][1], af[0][2], af[0][3], b0, b1);
                mma_tf32(acc[1][nt], af[1][0], af[1][1], af[1][2], af[1][3], b0, b1);
            }
        }
    }

    // epilogue: g_qkv flat row = p*128 + tile_row (windows are consecutive)
    const long row0 = (long)p * 128;
    #pragma unroll
    for (int mt = 0; mt < 2; mt++) {
        #pragma unroll
        for (int nt = 0; nt < 8; nt++) {
            const int col = dstcol + wn + nt * 8 + tg * 2;
            const long r1 = row0 + wm + mt * 16 + gq;
            *(float2*)(g_qkv + r1 * QKVW + col) =
                make_float2(acc[mt][nt][0], acc[mt][nt][1]);
            *(float2*)(g_qkv + (r1 + 8) * QKVW + col) =
                make_float2(acc[mt][nt][2], acc[mt][nt][3]);
        }
    }
}

// ---------------------------------------------------------------------------
// Kernel B: per-window attention with talking heads (fp32, unchanged).
// ---------------------------------------------------------------------------
#define AP 4168
#define AR 65

__global__ __launch_bounds__(256) void attn_kernel(
    const float* __restrict__ W_pre, const float* __restrict__ W_post)
{
    extern __shared__ float sm[];
    float4* s_kv4  = (float4*)sm;
    float*  s_attn = sm + 16640;
    float*  s_wpre  = sm + 16640 + 8 * AP;
    float*  s_wpost = sm + 16640 + 8 * AP + 64;
    float*  s_rsum  = sm + 16640 + 8 * AP + 128;

    const int win = blockIdx.x;
    const int tid = threadIdx.x;
    const int qrow = tid & 63;
    const int hp   = tid >> 6;
    const long rowbase = (long)win * 64;
    const float4* qkv4 = (const float4*)g_qkv;

    for (int idx = tid; idx < 64 * 64; idx += 256) {
        int s = idx >> 6, c4 = idx & 63;
        s_kv4[s * 65 + c4] = qkv4[(rowbase + s) * 192 + 64 + c4];
    }
    if (tid < 64) { s_wpre[tid] = W_pre[tid]; s_wpost[tid] = W_post[tid]; }

    float4 qr[16];
    #pragma unroll
    for (int j4 = 0; j4 < 16; j4++)
        qr[j4] = qkv4[(rowbase + qrow) * 192 + hp * 16 + j4];
    __syncthreads();

    const float scale = 0.17677669529663687f;
    for (int k = 0; k < 64; k++) {
        #pragma unroll
        for (int h2 = 0; h2 < 2; h2++) {
            int h = hp * 2 + h2;
            float acc = 0.f;
            #pragma unroll
            for (int d4 = 0; d4 < 8; ++d4) {
                float4 kv = s_kv4[k * 65 + h * 8 + d4];
                float4 qv = qr[h2 * 8 + d4];
                acc += qv.x * kv.x + qv.y * kv.y + qv.z * kv.z + qv.w * kv.w;
            }
            s_attn[h * AP + qrow * AR + k] = acc * scale;
        }
    }
    __syncthreads();

    #pragma unroll 1
    for (int i = 0; i < 16; i++) {
        int pidx = tid + (i << 8);
        int q = pidx >> 6, k = pidx & 63;
        float av[8], m[8];
        #pragma unroll
        for (int h = 0; h < 8; h++) av[h] = s_attn[h * AP + q * AR + k];
        #pragma unroll
        for (int h = 0; h < 8; h++) {
            float s = 0.f;
            #pragma unroll
            for (int h2 = 0; h2 < 8; h2++) s += av[h2] * s_wpre[h * 8 + h2];
            m[h] = __expf(s);
        }
        #pragma unroll
        for (int h = 0; h < 8; h++) s_attn[h * AP + q * AR + k] = m[h];
    }
    __syncthreads();

    #pragma unroll
    for (int i = 0; i < 2; i++) {
        int task = tid + (i << 8);
        int q = task >> 3, h = task & 7;
        float s = 0.f;
        #pragma unroll 8
        for (int k = 0; k < 64; k++) s += s_attn[h * AP + q * AR + k];
        s_rsum[task] = 1.0f / s;
    }
    __syncthreads();

    #pragma unroll 1
    for (int i = 0; i < 16; i++) {
        int pidx = tid + (i << 8);
        int q = pidx >> 6, k = pidx & 63;
        float av[8], m[8];
        #pragma unroll
        for (int h = 0; h < 8; h++)
            av[h] = s_attn[h * AP + q * AR + k] * s_rsum[q * 8 + h];
        #pragma unroll
        for (int h = 0; h < 8; h++) {
            float s = 0.f;
            #pragma unroll
            for (int h2 = 0; h2 < 8; h2++) s += av[h2] * s_wpost[h * 8 + h2];
            m[h] = s;
        }
        #pragma unroll
        for (int h = 0; h < 8; h++) s_attn[h * AP + q * AR + k] = m[h];
    }
    __syncthreads();

    for (int idx = tid; idx < 64 * 64; idx += 256) {
        int s = idx >> 6, c4 = idx & 63;
        s_kv4[s * 65 + c4] = qkv4[(rowbase + s) * 192 + 128 + c4];
    }
    __syncthreads();

    float4 o[16];
    #pragma unroll
    for (int j = 0; j < 16; j++) o[j] = make_float4(0.f, 0.f, 0.f, 0.f);
    const int h0 = hp * 2, h1 = hp * 2 + 1;
    for (int k = 0; k < 64; k++) {
        float a0 = s_attn[h0 * AP + qrow * AR + k];
        float a1 = s_attn[h1 * AP + qrow * AR + k];
        #pragma unroll
        for (int d4 = 0; d4 < 8; ++d4) {
            float4 v = s_kv4[k * 65 + h0 * 8 + d4];
            o[d4].x += a0 * v.x; o[d4].y += a0 * v.y;
            o[d4].z += a0 * v.z; o[d4].w += a0 * v.w;
        }
        #pragma unroll
        for (int d4 = 0; d4 < 8; ++d4) {
            float4 v = s_kv4[k * 65 + h1 * 8 + d4];
            o[8 + d4].x += a1 * v.x; o[8 + d4].y += a1 * v.y;
            o[8 + d4].z += a1 * v.z; o[8 + d4].w += a1 * v.w;
        }
    }
    float4* qkvw = (float4*)g_qkv;
    #pragma unroll
    for (int j4 = 0; j4 < 16; j4++)
        qkvw[(rowbase + qrow) * 192 + hp * 16 + j4] = o[j4];
}

// ---------------------------------------------------------------------------
// Kernel C (tf32 mma): out = unwindow(attn_out) @ W_proj^T + b_proj
// ---------------------------------------------------------------------------
__global__ __launch_bounds__(256) void proj_mma(
    const float* __restrict__ W_proj, const float* __restrict__ b_proj,
    float* __restrict__ out)
{
    extern __shared__ float sm[];
    const int tid = threadIdx.x;
    const long row0 = (long)blockIdx.x * 128;
    const int colb = blockIdx.y * 128;

    const int ldr = tid >> 1;
    const int ldc = (tid & 1) << 4;
    long row = row0 + ldr;
    int b = (int)(row >> 14);
    int n = (int)(row & 16383);
    int i = n >> 7, j = n & 127;
    int srcrow = ((b << 8) + (i >> 3) * 16 + (j >> 3)) * 64 + (i & 7) * 8 + (j & 7);
    const float* a_src0 = g_qkv + (long)srcrow * QKVW + ldc;
    const float* b_src0 = W_proj + (long)(colb + ldr) * 256 + ldc;

    uint32_t smem_base = (uint32_t)__cvta_generic_to_shared(sm);
    uint32_t a_dst0 = smem_base + (uint32_t)(ldr * TSTRIDE + ldc) * 4;
    uint32_t b_dst0 = a_dst0 + TILE_F * 4;

    const int lane = tid & 31, w = tid >> 5;
    const int wm = (w >> 1) * 32;
    const int wn = (w & 1) * 64;
    const int gq = lane >> 2, tg = lane & 3;

    float acc[2][8][4];
    #pragma unroll
    for (int mt = 0; mt < 2; mt++)
        #pragma unroll
        for (int nt = 0; nt < 8; nt++)
            #pragma unroll
            for (int q = 0; q < 4; q++) acc[mt][nt][q] = 0.f;

    {
        #pragma unroll
        for (int k = 0; k < 4; k++) CPA16(a_dst0 + k * 16, a_src0 + k * 4);
        #pragma unroll
        for (int k = 0; k < 4; k++) CPA16(b_dst0 + k * 16, b_src0 + k * 4);
        CP_COMMIT();
    }

    for (int kb = 0; kb < 8; ++kb) {
        CP_WAIT0();
        __syncthreads();
        if (kb < 7) {
            uint32_t off = (uint32_t)(((kb + 1) & 1) * BUF_F * 4);
            const float* as = a_src0 + (kb + 1) * 32;
            const float* bs = b_src0 + (kb + 1) * 32;
            #pragma unroll
            for (int k = 0; k < 4; k++) CPA16(a_dst0 + off + k * 16, as + k * 4);
            #pragma unroll
            for (int k = 0; k < 4; k++) CPA16(b_dst0 + off + k * 16, bs + k * 4);
            CP_COMMIT();
        }
        const float* sA = sm + (kb & 1) * BUF_F;
        const float* sB = sA + TILE_F;

        #pragma unroll
        for (int ks = 0; ks < 4; ++ks) {
            const int k0 = ks * 8;
            uint32_t af[2][4];
            #pragma unroll
            for (int mt = 0; mt < 2; mt++) {
                const int r0 = wm + mt * 16;
                af[mt][0] = f2tf(sA[(r0 + gq)     * TSTRIDE + k0 + tg]);
                af[mt][1] = f2tf(sA[(r0 + gq + 8) * TSTRIDE + k0 + tg]);
                af[mt][2] = f2tf(sA[(r0 + gq)     * TSTRIDE + k0 + tg + 4]);
                af[mt][3] = f2tf(sA[(r0 + gq + 8) * TSTRIDE + k0 + tg + 4]);
            }
            #pragma unroll
            for (int nt = 0; nt < 8; nt++) {
                const int nb = wn + nt * 8;
                uint32_t b0 = f2tf(sB[(nb + gq) * TSTRIDE + k0 + tg]);
                uint32_t b1 = f2tf(sB[(nb + gq) * TSTRIDE + k0 + tg + 4]);
                mma_tf32(acc[0][nt], af[0][0], af[0][1], af[0][2], af[0][3], b0, b1);
                mma_tf32(acc[1][nt], af[1][0], af[1][1], af[1][2], af[1][3], b0, b1);
            }
        }
    }

    #pragma unroll
    for (int mt = 0; mt < 2; mt++) {
        #pragma unroll
        for (int nt = 0; nt < 8; nt++) {
            const int col = colb + wn + nt * 8 + tg * 2;
            const float2 bv = *(const float2*)(b_proj + col);
            const long r1 = row0 + wm + mt * 16 + gq;
            *(float2*)(out + r1 * NC + col) =
                make_float2(acc[mt][nt][0] + bv.x, acc[mt][nt][1] + bv.y);
            *(float2*)(out + (r1 + 8) * NC + col) =
                make_float2(acc[mt][nt][2] + bv.x, acc[mt][nt][3] + bv.y);
        }
    }
}

// ---------------------------------------------------------------------------
extern "C" void kernel_launch(void* const* d_in, const int* in_sizes, int n_in,
                              void* d_out, int out_size)
{
    const float* x      = (const float*)d_in[0];
    const float* query  = (const float*)d_in[1];
    const float* W_qk   = (const float*)d_in[2];
    const float* W_v    = (const float*)d_in[3];
    const float* W_proj = (const float*)d_in[4];
    const float* b_proj = (const float*)d_in[5];
    const float* W_pre  = (const float*)d_in[6];
    const float* W_post = (const float*)d_in[7];
    float* out = (float*)d_out;

    const int SMEM_ATTN = (16640 + 8 * AP + 128 + 512) * 4;

    cudaFuncSetAttribute(qkv_mma,  cudaFuncAttributeMaxDynamicSharedMemorySize, SMEM_MMA_BYTES);
    cudaFuncSetAttribute(attn_kernel, cudaFuncAttributeMaxDynamicSharedMemorySize, SMEM_ATTN);
    cudaFuncSetAttribute(proj_mma, cudaFuncAttributeMaxDynamicSharedMemorySize, SMEM_MMA_BYTES);

    qkv_mma<<<dim3(NWIN / 2, 6), 256, SMEM_MMA_BYTES>>>(x, query, W_qk, W_v);
    attn_kernel<<<NWIN, 256, SMEM_ATTN>>>(W_pre, W_post);
    proj_mma<<<dim3(NWIN / 2, 2), 256, SMEM_MMA_BYTES>>>(W_proj, b_proj, out);
}

// round 3
// speedup vs baseline: 5.9813x; 1.2765x over previous
#include <cuda_runtime.h>
#include <cstdint>

// Problem constants
#define NB    8
#define NTOK  16384
#define NC    256
#define NWIN  2048    // B * (16x16 windows)
#define QKVW  768     // q(256) | k(256) | v(256)

// Scratch: windowed Q|K|V rows. Attention output overwrites the Q columns.
__device__ float g_qkv[(size_t)NWIN * 64 * QKVW];
// tf32-rounded weights
__device__ float g_wqk[512 * 256];
__device__ float g_wv[256 * 256];
__device__ float g_wproj[256 * 256];

// ---------------------------------------------------------------------------
// tf32 helpers
// ---------------------------------------------------------------------------
__device__ __forceinline__ uint32_t f2tf(float f) {
    uint32_t u;
    asm("cvt.rna.tf32.f32 %0, %1;" : "=r"(u) : "f"(f));
    return u;
}
__device__ __forceinline__ float ftf(float f) {   // tf32-rounded fp32 value
    uint32_t u = f2tf(f);
    return __uint_as_float(u);
}
__device__ __forceinline__ void mma_tf32(float c[4],
    uint32_t a0, uint32_t a1, uint32_t a2, uint32_t a3,
    uint32_t b0, uint32_t b1)
{
    asm volatile(
        "mma.sync.aligned.m16n8k8.row.col.f32.tf32.tf32.f32 "
        "{%0,%1,%2,%3},{%4,%5,%6,%7},{%8,%9},{%0,%1,%2,%3};"
        : "+f"(c[0]), "+f"(c[1]), "+f"(c[2]), "+f"(c[3])
        : "r"(a0), "r"(a1), "r"(a2), "r"(a3), "r"(b0), "r"(b1));
}
#define CPA16(dst, src) \
    asm volatile("cp.async.cg.shared.global [%0],[%1],16;" :: "r"(dst), "l"(src))
#define CP_COMMIT() asm volatile("cp.async.commit_group;")
#define CP_WAIT0()  asm volatile("cp.async.wait_group 0;" ::: "memory")

#define TSTRIDE 36
#define TILE_F  (128 * TSTRIDE)
#define BUF_F   (2 * TILE_F)
#define SMEM_MMA_BYTES (2 * BUF_F * 4)

// ---------------------------------------------------------------------------
// Weight pre-conversion to tf32-rounded fp32
// ---------------------------------------------------------------------------
__global__ __launch_bounds__(256) void cvt_weights(
    const float* __restrict__ wqk, const float* __restrict__ wv,
    const float* __restrict__ wproj)
{
    int idx = blockIdx.x * 256 + threadIdx.x;   // 0..65535, 4 elems each
    #pragma unroll
    for (int i = 0; i < 4; i++) {
        int e = idx * 4 + i;
        if (e < 131072)           g_wqk[e] = ftf(wqk[e]);
        else if (e < 196608)      g_wv[e - 131072] = ftf(wv[e - 131072]);
        else                      g_wproj[e - 196608] = ftf(wproj[e - 196608]);
    }
}

// ---------------------------------------------------------------------------
// Kernel A (tf32 mma): windowed-gather GEMM producing Q|K|V.
// ---------------------------------------------------------------------------
__global__ __launch_bounds__(256) void qkv_mma(
    const float* __restrict__ x, const float* __restrict__ query)
{
    extern __shared__ float sm[];
    const int tid = threadIdx.x;
    const int p   = blockIdx.x;
    const int cb  = blockIdx.y;

    const float* in = (cb < 4) ? query : x;
    const float* Wt = (cb < 4) ? (g_wqk + (long)cb * 128 * 256)
                               : (g_wv  + (long)(cb - 4) * 128 * 256);
    const int dstcol = (cb < 4) ? cb * 128 : 512 + (cb - 4) * 128;

    const int ldr = tid >> 1;
    const int ldc = (tid & 1) << 4;
    int win = p * 2 + (ldr >> 6);
    int s   = ldr & 63;
    int b   = win >> 8, g = win & 255;
    int n   = ((g >> 4) * 8 + (s >> 3)) * 128 + (g & 15) * 8 + (s & 7);
    const float* a_src0 = in + ((long)b * NTOK + n) * 256 + ldc;
    const float* b_src0 = Wt + (long)ldr * 256 + ldc;

    uint32_t smem_base = (uint32_t)__cvta_generic_to_shared(sm);
    uint32_t a_dst0 = smem_base + (uint32_t)(ldr * TSTRIDE + ldc) * 4;
    uint32_t b_dst0 = a_dst0 + TILE_F * 4;

    const int lane = tid & 31, w = tid >> 5;
    const int wm = (w >> 1) * 32;
    const int wn = (w & 1) * 64;
    const int gq = lane >> 2, tg = lane & 3;

    float acc[2][8][4];
    #pragma unroll
    for (int mt = 0; mt < 2; mt++)
        #pragma unroll
        for (int nt = 0; nt < 8; nt++)
            #pragma unroll
            for (int q = 0; q < 4; q++) acc[mt][nt][q] = 0.f;

    {
        #pragma unroll
        for (int i = 0; i < 4; i++) CPA16(a_dst0 + i * 16, a_src0 + i * 4);
        #pragma unroll
        for (int i = 0; i < 4; i++) CPA16(b_dst0 + i * 16, b_src0 + i * 4);
        CP_COMMIT();
    }

    for (int kb = 0; kb < 8; ++kb) {
        CP_WAIT0();
        __syncthreads();
        if (kb < 7) {
            uint32_t off = (uint32_t)(((kb + 1) & 1) * BUF_F * 4);
            const float* as = a_src0 + (kb + 1) * 32;
            const float* bs = b_src0 + (kb + 1) * 32;
            #pragma unroll
            for (int i = 0; i < 4; i++) CPA16(a_dst0 + off + i * 16, as + i * 4);
            #pragma unroll
            for (int i = 0; i < 4; i++) CPA16(b_dst0 + off + i * 16, bs + i * 4);
            CP_COMMIT();
        }
        const float* sA = sm + (kb & 1) * BUF_F;
        const float* sB = sA + TILE_F;

        #pragma unroll
        for (int ks = 0; ks < 4; ++ks) {
            const int k0 = ks * 8;
            uint32_t af[2][4];
            #pragma unroll
            for (int mt = 0; mt < 2; mt++) {
                const int r0 = wm + mt * 16;
                af[mt][0] = f2tf(sA[(r0 + gq)     * TSTRIDE + k0 + tg]);
                af[mt][1] = f2tf(sA[(r0 + gq + 8) * TSTRIDE + k0 + tg]);
                af[mt][2] = f2tf(sA[(r0 + gq)     * TSTRIDE + k0 + tg + 4]);
                af[mt][3] = f2tf(sA[(r0 + gq + 8) * TSTRIDE + k0 + tg + 4]);
            }
            #pragma unroll
            for (int nt = 0; nt < 8; nt++) {
                const int nb = wn + nt * 8;
                uint32_t b0 = __float_as_uint(sB[(nb + gq) * TSTRIDE + k0 + tg]);
                uint32_t b1 = __float_as_uint(sB[(nb + gq) * TSTRIDE + k0 + tg + 4]);
                mma_tf32(acc[0][nt], af[0][0], af[0][1], af[0][2], af[0][3], b0, b1);
                mma_tf32(acc[1][nt], af[1][0], af[1][1], af[1][2], af[1][3], b0, b1);
            }
        }
    }

    const long row0 = (long)p * 128;
    #pragma unroll
    for (int mt = 0; mt < 2; mt++) {
        #pragma unroll
        for (int nt = 0; nt < 8; nt++) {
            const int col = dstcol + wn + nt * 8 + tg * 2;
            const long r1 = row0 + wm + mt * 16 + gq;
            *(float2*)(g_qkv + r1 * QKVW + col) =
                make_float2(acc[mt][nt][0], acc[mt][nt][1]);
            *(float2*)(g_qkv + (r1 + 8) * QKVW + col) =
                make_float2(acc[mt][nt][2], acc[mt][nt][3]);
        }
    }
}

// ---------------------------------------------------------------------------
// Kernel B: per-window attention, tf32 mma for scores and attn@V.
// One block per window; warp w = head h. Scalar talking-heads mixes.
// Output (tf32-rounded) overwrites Q columns of g_qkv.
// ---------------------------------------------------------------------------
#define SKR 260              // s_k / s_q row stride (floats)
#define PL  4232             // attn plane stride (floats)
#define RS  66               // attn row stride (floats)
// smem float offsets
#define OFF_K     0
#define OFF_ATTN  16640
#define OFF_WPRE  (16640 + 8 * PL)          // 50496
#define OFF_WPOST (OFF_WPRE + 64)
#define OFF_RSUM  (OFF_WPRE + 128)
#define SMEM_ATTN_F (OFF_RSUM + 512)        // 51136 floats
#define SMEM_ATTN_BYTES (SMEM_ATTN_F * 4)   // 204544

__global__ __launch_bounds__(256) void attn_kernel(
    const float* __restrict__ W_pre, const float* __restrict__ W_post)
{
    extern __shared__ float sm[];
    float4* s_k4 = (float4*)(sm + OFF_K);
    float4* s_q4 = (float4*)(sm + OFF_ATTN);   // Q staged over attn region
    float*  s_attn  = sm + OFF_ATTN;
    float*  s_wpre  = sm + OFF_WPRE;
    float*  s_wpost = sm + OFF_WPOST;
    float*  s_rsum  = sm + OFF_RSUM;

    const int tid  = threadIdx.x;
    const int lane = tid & 31;
    const int h    = tid >> 5;                 // warp = head
    const int gq = lane >> 2, tg = lane & 3;
    const int h32 = h * 32;
    const long rowbase = (long)blockIdx.x * 64;
    const float4* qkv4 = (const float4*)g_qkv; // row stride 192 float4

    // Stage Q (cols 0..63 f4) and K (cols 64..127 f4)
    for (int idx = tid; idx < 64 * 64; idx += 256) {
        int s = idx >> 6, c4 = idx & 63;
        s_q4[s * 65 + c4] = qkv4[(rowbase + s) * 192 + c4];
        s_k4[s * 65 + c4] = qkv4[(rowbase + s) * 192 + 64 + c4];
    }
    if (tid < 64) { s_wpre[tid] = W_pre[tid]; s_wpost[tid] = W_post[tid]; }
    __syncthreads();

    // ---- scores: S_h = Q_h @ K_h^T  (M=64,N=64,K=32) ----
    const float* sq = sm + OFF_ATTN;
    const float* sk = sm + OFF_K;
    float acc[4][8][4];
    #pragma unroll
    for (int mt = 0; mt < 4; mt++)
        #pragma unroll
        for (int nt = 0; nt < 8; nt++)
            #pragma unroll
            for (int q = 0; q < 4; q++) acc[mt][nt][q] = 0.f;

    #pragma unroll
    for (int ks = 0; ks < 4; ++ks) {
        const int k0 = ks * 8;
        uint32_t a[4][4];
        #pragma unroll
        for (int mt = 0; mt < 4; mt++) {
            const int r0 = mt * 16;
            a[mt][0] = f2tf(sq[(r0 + gq)     * SKR + h32 + k0 + tg]);
            a[mt][1] = f2tf(sq[(r0 + gq + 8) * SKR + h32 + k0 + tg]);
            a[mt][2] = f2tf(sq[(r0 + gq)     * SKR + h32 + k0 + tg + 4]);
            a[mt][3] = f2tf(sq[(r0 + gq + 8) * SKR + h32 + k0 + tg + 4]);
        }
        #pragma unroll
        for (int nt = 0; nt < 8; nt++) {
            const int nb = nt * 8;
            uint32_t b0 = f2tf(sk[(nb + gq) * SKR + h32 + k0 + tg]);
            uint32_t b1 = f2tf(sk[(nb + gq) * SKR + h32 + k0 + tg + 4]);
            #pragma unroll
            for (int mt = 0; mt < 4; mt++)
                mma_tf32(acc[mt][nt], a[mt][0], a[mt][1], a[mt][2], a[mt][3], b0, b1);
        }
    }
    __syncthreads();   // all warps done reading Q/K region

    // STS scores (scaled) into plane h; stage V over K buffer
    const float scale = 0.17677669529663687f;   // 32^-0.5
    float* pl = sm + OFF_ATTN + h * PL;
    #pragma unroll
    for (int mt = 0; mt < 4; mt++) {
        #pragma unroll
        for (int nt = 0; nt < 8; nt++) {
            const int q0 = mt * 16 + gq, c = nt * 8 + 2 * tg;
            *(float2*)&pl[q0 * RS + c] =
                make_float2(acc[mt][nt][0] * scale, acc[mt][nt][1] * scale);
            *(float2*)&pl[(q0 + 8) * RS + c] =
                make_float2(acc[mt][nt][2] * scale, acc[mt][nt][3] * scale);
        }
    }
    for (int idx = tid; idx < 64 * 64; idx += 256) {
        int s = idx >> 6, c4 = idx & 63;
        s_k4[s * 65 + c4] = qkv4[(rowbase + s) * 192 + 128 + c4];   // V
    }
    __syncthreads();

    // ---- pre-mix (heads) + exp ----
    #pragma unroll 1
    for (int i = 0; i < 16; i++) {
        int pidx = tid + (i << 8);
        int q = pidx >> 6, k = pidx & 63;
        float av[8], m[8];
        #pragma unroll
        for (int hh = 0; hh < 8; hh++) av[hh] = s_attn[hh * PL + q * RS + k];
        #pragma unroll
        for (int hh = 0; hh < 8; hh++) {
            float s = 0.f;
            #pragma unroll
            for (int h2 = 0; h2 < 8; h2++) s += av[h2] * s_wpre[hh * 8 + h2];
            m[hh] = __expf(s);
        }
        #pragma unroll
        for (int hh = 0; hh < 8; hh++) s_attn[hh * PL + q * RS + k] = m[hh];
    }
    __syncthreads();

    // ---- softmax denominator ----
    #pragma unroll
    for (int i = 0; i < 2; i++) {
        int task = tid + (i << 8);
        int q = task >> 3, hh = task & 7;
        float s = 0.f;
        #pragma unroll 8
        for (int k = 0; k < 64; k++) s += s_attn[hh * PL + q * RS + k];
        s_rsum[task] = 1.0f / s;
    }
    __syncthreads();

    // ---- normalize + post-mix ----
    #pragma unroll 1
    for (int i = 0; i < 16; i++) {
        int pidx = tid + (i << 8);
        int q = pidx >> 6, k = pidx & 63;
        float av[8], m[8];
        #pragma unroll
        for (int hh = 0; hh < 8; hh++)
            av[hh] = s_attn[hh * PL + q * RS + k] * s_rsum[q * 8 + hh];
        #pragma unroll
        for (int hh = 0; hh < 8; hh++) {
            float s = 0.f;
            #pragma unroll
            for (int h2 = 0; h2 < 8; h2++) s += av[h2] * s_wpost[hh * 8 + h2];
            m[hh] = s;
        }
        #pragma unroll
        for (int hh = 0; hh < 8; hh++) s_attn[hh * PL + q * RS + k] = m[hh];
    }
    __syncthreads();

    // ---- O_h = A_h @ V_h  (M=64, N=32, K=64) ----
    float acc2[4][4][4];
    #pragma unroll
    for (int mt = 0; mt < 4; mt++)
        #pragma unroll
        for (int nt = 0; nt < 4; nt++)
            #pragma unroll
            for (int q = 0; q < 4; q++) acc2[mt][nt][q] = 0.f;

    #pragma unroll
    for (int ks = 0; ks < 8; ++ks) {
        const int k0 = ks * 8;
        uint32_t a[4][4];
        #pragma unroll
        for (int mt = 0; mt < 4; mt++) {
            const int r0 = mt * 16;
            a[mt][0] = f2tf(pl[(r0 + gq)     * RS + k0 + tg]);
            a[mt][1] = f2tf(pl[(r0 + gq + 8) * RS + k0 + tg]);
            a[mt][2] = f2tf(pl[(r0 + gq)     * RS + k0 + tg + 4]);
            a[mt][3] = f2tf(pl[(r0 + gq + 8) * RS + k0 + tg + 4]);
        }
        #pragma unroll
        for (int nt = 0; nt < 4; nt++) {
            const int nb = nt * 8;
            uint32_t b0 = f2tf(sk[(k0 + tg)     * SKR + h32 + nb + gq]);
            uint32_t b1 = f2tf(sk[(k0 + tg + 4) * SKR + h32 + nb + gq]);
            #pragma unroll
            for (int mt = 0; mt < 4; mt++)
                mma_tf32(acc2[mt][nt], a[mt][0], a[mt][1], a[mt][2], a[mt][3], b0, b1);
        }
    }

    // epilogue: write O (tf32-rounded) over Q columns
    #pragma unroll
    for (int mt = 0; mt < 4; mt++) {
        #pragma unroll
        for (int nt = 0; nt < 4; nt++) {
            const int col = h32 + nt * 8 + 2 * tg;
            const long r1 = rowbase + mt * 16 + gq;
            *(float2*)(g_qkv + r1 * QKVW + col) =
                make_float2(ftf(acc2[mt][nt][0]), ftf(acc2[mt][nt][1]));
            *(float2*)(g_qkv + (r1 + 8) * QKVW + col) =
                make_float2(ftf(acc2[mt][nt][2]), ftf(acc2[mt][nt][3]));
        }
    }
}

// ---------------------------------------------------------------------------
// Kernel C (tf32 mma): out = unwindow(attn_out) @ W_proj^T + b_proj
// A and B are pre-rounded to tf32 -> no CVTs in the loop.
// ---------------------------------------------------------------------------
__global__ __launch_bounds__(256) void proj_mma(
    const float* __restrict__ b_proj, float* __restrict__ out)
{
    extern __shared__ float sm[];
    const int tid = threadIdx.x;
    const long row0 = (long)blockIdx.x * 128;
    const int colb = blockIdx.y * 128;

    const int ldr = tid >> 1;
    const int ldc = (tid & 1) << 4;
    long row = row0 + ldr;
    int b = (int)(row >> 14);
    int n = (int)(row & 16383);
    int i = n >> 7, j = n & 127;
    int srcrow = ((b << 8) + (i >> 3) * 16 + (j >> 3)) * 64 + (i & 7) * 8 + (j & 7);
    const float* a_src0 = g_qkv + (long)srcrow * QKVW + ldc;
    const float* b_src0 = g_wproj + (long)(colb + ldr) * 256 + ldc;

    uint32_t smem_base = (uint32_t)__cvta_generic_to_shared(sm);
    uint32_t a_dst0 = smem_base + (uint32_t)(ldr * TSTRIDE + ldc) * 4;
    uint32_t b_dst0 = a_dst0 + TILE_F * 4;

    const int lane = tid & 31, w = tid >> 5;
    const int wm = (w >> 1) * 32;
    const int wn = (w & 1) * 64;
    const int gq = lane >> 2, tg = lane & 3;

    float acc[2][8][4];
    #pragma unroll
    for (int mt = 0; mt < 2; mt++)
        #pragma unroll
        for (int nt = 0; nt < 8; nt++)
            #pragma unroll
            for (int q = 0; q < 4; q++) acc[mt][nt][q] = 0.f;

    {
        #pragma unroll
        for (int k = 0; k < 4; k++) CPA16(a_dst0 + k * 16, a_src0 + k * 4);
        #pragma unroll
        for (int k = 0; k < 4; k++) CPA16(b_dst0 + k * 16, b_src0 + k * 4);
        CP_COMMIT();
    }

    for (int kb = 0; kb < 8; ++kb) {
        CP_WAIT0();
        __syncthreads();
        if (kb < 7) {
            uint32_t off = (uint32_t)(((kb + 1) & 1) * BUF_F * 4);
            const float* as = a_src0 + (kb + 1) * 32;
            const float* bs = b_src0 + (kb + 1) * 32;
            #pragma unroll
            for (int k = 0; k < 4; k++) CPA16(a_dst0 + off + k * 16, as + k * 4);
            #pragma unroll
            for (int k = 0; k < 4; k++) CPA16(b_dst0 + off + k * 16, bs + k * 4);
            CP_COMMIT();
        }
        const float* sA = sm + (kb & 1) * BUF_F;
        const float* sB = sA + TILE_F;

        #pragma unroll
        for (int ks = 0; ks < 4; ++ks) {
            const int k0 = ks * 8;
            uint32_t af[2][4];
            #pragma unroll
            for (int mt = 0; mt < 2; mt++) {
                const int r0 = wm + mt * 16;
                af[mt][0] = __float_as_uint(sA[(r0 + gq)     * TSTRIDE + k0 + tg]);
                af[mt][1] = __float_as_uint(sA[(r0 + gq + 8) * TSTRIDE + k0 + tg]);
                af[mt][2] = __float_as_uint(sA[(r0 + gq)     * TSTRIDE + k0 + tg + 4]);
                af[mt][3] = __float_as_uint(sA[(r0 + gq + 8) * TSTRIDE + k0 + tg + 4]);
            }
            #pragma unroll
            for (int nt = 0; nt < 8; nt++) {
                const int nb = wn + nt * 8;
                uint32_t b0 = __float_as_uint(sB[(nb + gq) * TSTRIDE + k0 + tg]);
                uint32_t b1 = __float_as_uint(sB[(nb + gq) * TSTRIDE + k0 + tg + 4]);
                mma_tf32(acc[0][nt], af[0][0], af[0][1], af[0][2], af[0][3], b0, b1);
                mma_tf32(acc[1][nt], af[1][0], af[1][1], af[1][2], af[1][3], b0, b1);
            }
        }
    }

    #pragma unroll
    for (int mt = 0; mt < 2; mt++) {
        #pragma unroll
        for (int nt = 0; nt < 8; nt++) {
            const int col = colb + wn + nt * 8 + tg * 2;
            const float2 bv = *(const float2*)(b_proj + col);
            const long r1 = row0 + wm + mt * 16 + gq;
            *(float2*)(out + r1 * NC + col) =
                make_float2(acc[mt][nt][0] + bv.x, acc[mt][nt][1] + bv.y);
            *(float2*)(out + (r1 + 8) * NC + col) =
                make_float2(acc[mt][nt][2] + bv.x, acc[mt][nt][3] + bv.y);
        }
    }
}

// ---------------------------------------------------------------------------
extern "C" void kernel_launch(void* const* d_in, const int* in_sizes, int n_in,
                              void* d_out, int out_size)
{
    const float* x      = (const float*)d_in[0];
    const float* query  = (const float*)d_in[1];
    const float* W_qk   = (const float*)d_in[2];
    const float* W_v    = (const float*)d_in[3];
    const float* W_proj = (const float*)d_in[4];
    const float* b_proj = (const float*)d_in[5];
    const float* W_pre  = (const float*)d_in[6];
    const float* W_post = (const float*)d_in[7];
    float* out = (float*)d_out;

    cudaFuncSetAttribute(qkv_mma,  cudaFuncAttributeMaxDynamicSharedMemorySize, SMEM_MMA_BYTES);
    cudaFuncSetAttribute(attn_kernel, cudaFuncAttributeMaxDynamicSharedMemorySize, SMEM_ATTN_BYTES);
    cudaFuncSetAttribute(proj_mma, cudaFuncAttributeMaxDynamicSharedMemorySize, SMEM_MMA_BYTES);

    cvt_weights<<<256, 256>>>(W_qk, W_v, W_proj);
    qkv_mma<<<dim3(NWIN / 2, 6), 256, SMEM_MMA_BYTES>>>(x, query);
    attn_kernel<<<NWIN, 256, SMEM_ATTN_BYTES>>>(W_pre, W_post);
    proj_mma<<<dim3(NWIN / 2, 2), 256, SMEM_MMA_BYTES>>>(b_proj, out);
}